// round 4
// baseline (speedup 1.0000x reference)
#include <cuda_runtime.h>
#include <math.h>

#define DIM   512
#define NQ    64
#define NB    2048
#define NM    131328            /* 512*513/2 */
#define ESLICES 8
#define ETILE  64               /* e per slice */
#define BTILE  64
#define PSTRIDE 516             /* padded P row stride (floats), keeps 16B align, kills bank conflicts */
#define PRE_BLOCKS 1024

/* ---- scratch (static device globals; no allocation APIs used) ---- */
__device__ float g_W[(size_t)DIM * DIM * NQ];        /* [e][d][k]  64 MB */
__device__ float g_grad_part[(size_t)ESLICES * NB * NQ]; /* 4 MB */
__device__ float g_pg_part  [(size_t)ESLICES * NB * NQ]; /* 4 MB */
__device__ float g_nsq_part [(size_t)PRE_BLOCKS * NQ];
__device__ float g_norm[NQ];

/* ============================================================
 * Kernel 1: build scaled symmetric matrices W[e][d][k] and
 * partial column norms of q_coefs. Fully coalesced both ways.
 * ============================================================ */
__global__ __launch_bounds__(256) void hsq_prep_kernel(const float* __restrict__ q_coefs)
{
    const int t  = threadIdx.x;
    const int k  = t & 63;      /* quadric index */
    const int ms = t >> 6;      /* mono sub-slot 0..3 */
    float nsq = 0.0f;

    for (int base = blockIdx.x * 4; base < NM; base += gridDim.x * 4) {
        const int m = base + ms;
        if (m < NM) {
            const float q = q_coefs[(size_t)m * NQ + k];
            /* invert flat triu index m -> (i, j), i <= j, rowstart(i)=i*DIM - i(i-1)/2 */
            int i = (int)((2.0f * DIM + 1.0f -
                           sqrtf((float)(2 * DIM + 1) * (2 * DIM + 1) - 8.0f * (float)m)) * 0.5f);
            if (i < 0) i = 0;
            if (i > DIM - 1) i = DIM - 1;
            while (i > 0 && (i * DIM - (i * (i - 1)) / 2) > m) i--;
            while (i < DIM - 1 && ((i + 1) * DIM - ((i + 1) * i) / 2) <= m) i++;
            const int j = i + (m - (i * DIM - (i * (i - 1)) / 2));

            /* m_scaled: diag = 2*q (coef 1 * dm 2), off-diag = sqrt2*q (coef sqrt2 * dm 1) */
            const float v = q * ((i == j) ? 2.0f : 1.4142135623730951f);
            g_W[((size_t)i * DIM + j) * NQ + k] = v;
            if (i != j)
                g_W[((size_t)j * DIM + i) * NQ + k] = v;
            nsq += q * q;       /* norm uses RAW q_coefs */
        }
    }

    __shared__ float red[256];
    red[t] = nsq;
    __syncthreads();
    if (ms == 0)
        g_nsq_part[(size_t)blockIdx.x * NQ + k] =
            red[k] + red[64 + k] + red[128 + k] + red[192 + k];
}

/* ============================================================
 * Kernel 2: finalize norms (fixed-order, deterministic)
 * ============================================================ */
__global__ void hsq_norm_kernel()
{
    const int k = threadIdx.x;  /* 64 threads */
    float s = 0.0f;
    for (int b = 0; b < PRE_BLOCKS; b++)
        s += g_nsq_part[(size_t)b * NQ + k];
    g_norm[k] = sqrtf(s);
}

/* ============================================================
 * Kernel 3: main contraction.
 * CTA: 64 b-rows x 64 k-cols x one 64-wide e-slice.
 * Per e: g[b,k] = sum_d p[b,d]*W[e,d,k] + l[e,k]
 * fused:  grad[b,k] += g^2 ;  pg[b,k] += p[b,e]*g
 * ============================================================ */
__global__ __launch_bounds__(256) void hsq_main_kernel(const float* __restrict__ points,
                                                       const float* __restrict__ l_coefs)
{
    extern __shared__ float ps[];            /* [BTILE][PSTRIDE] */
    const int bt = blockIdx.x;               /* 0..31 */
    const int es = blockIdx.y;               /* 0..7  */
    const int b0 = bt * BTILE;
    const int e0 = es * ETILE;
    const int t  = threadIdx.x;
    const int kc = t & 15;                   /* k block: 4*kc .. 4*kc+3 */
    const int br = t >> 4;                   /* b block: 4*br .. 4*br+3 */

    /* stage P tile (coalesced) */
    for (int idx = t; idx < BTILE * DIM; idx += 256) {
        const int r = idx >> 9;
        const int c = idx & 511;
        ps[r * PSTRIDE + c] = points[(size_t)(b0 + r) * DIM + c];
    }
    __syncthreads();

    float grad[4][4] = {};
    float pg[4][4]   = {};

    const float* pb = ps + (br * 4) * PSTRIDE;

    for (int e = e0; e < e0 + ETILE; e++) {
        float acc[4][4] = {};
        const float* wb = g_W + (size_t)e * DIM * NQ + kc * 4;

        #pragma unroll 2
        for (int d = 0; d < DIM; d += 4) {
            float4 wv[4];
            #pragma unroll
            for (int u = 0; u < 4; u++)
                wv[u] = *(const float4*)(wb + (size_t)(d + u) * NQ);

            float pr[4][4];
            #pragma unroll
            for (int i = 0; i < 4; i++) {
                const float4 pv = *(const float4*)(pb + i * PSTRIDE + d);
                pr[i][0] = pv.x; pr[i][1] = pv.y; pr[i][2] = pv.z; pr[i][3] = pv.w;
            }

            #pragma unroll
            for (int u = 0; u < 4; u++) {
                const float4 wq = wv[u];
                #pragma unroll
                for (int i = 0; i < 4; i++) {
                    acc[i][0] = fmaf(pr[i][u], wq.x, acc[i][0]);
                    acc[i][1] = fmaf(pr[i][u], wq.y, acc[i][1]);
                    acc[i][2] = fmaf(pr[i][u], wq.z, acc[i][2]);
                    acc[i][3] = fmaf(pr[i][u], wq.w, acc[i][3]);
                }
            }
        }

        const float4 lv = __ldg((const float4*)(l_coefs + (size_t)e * NQ + kc * 4));
        const float lk[4] = { lv.x, lv.y, lv.z, lv.w };

        #pragma unroll
        for (int i = 0; i < 4; i++) {
            const float pe = pb[i * PSTRIDE + e];
            #pragma unroll
            for (int j = 0; j < 4; j++) {
                const float g = acc[i][j] + lk[j];
                grad[i][j] = fmaf(g, g, grad[i][j]);
                pg[i][j]   = fmaf(pe, g, pg[i][j]);
            }
        }
    }

    #pragma unroll
    for (int i = 0; i < 4; i++) {
        const size_t o = ((size_t)es * NB + (b0 + br * 4 + i)) * NQ + kc * 4;
        *(float4*)(g_grad_part + o) = make_float4(grad[i][0], grad[i][1], grad[i][2], grad[i][3]);
        *(float4*)(g_pg_part   + o) = make_float4(pg[i][0],   pg[i][1],   pg[i][2],   pg[i][3]);
    }
}

/* ============================================================
 * Kernel 4: epilogue — sum partials (fixed order), p.l dot,
 * values, final score formula.
 * ============================================================ */
__global__ __launch_bounds__(256) void hsq_score_kernel(const float* __restrict__ points,
                                                        const float* __restrict__ l_coefs,
                                                        const float* __restrict__ free_coefs,
                                                        float* __restrict__ out)
{
    __shared__ float psh[4 * DIM];
    const int b0 = blockIdx.x * 4;
    const int t  = threadIdx.x;

    for (int idx = t; idx < 4 * DIM; idx += 256)
        psh[idx] = points[(size_t)b0 * DIM + idx];
    __syncthreads();

    const int k  = t & 63;
    const int bi = t >> 6;
    const int b  = b0 + bi;
    const float* pr = psh + bi * DIM;

    float pl = 0.0f;
    #pragma unroll 8
    for (int d = 0; d < DIM; d++)
        pl = fmaf(pr[d], l_coefs[(size_t)d * NQ + k], pl);

    float grad = 0.0f, pg = 0.0f;
    #pragma unroll
    for (int s = 0; s < ESLICES; s++) {
        const size_t o = ((size_t)s * NB + b) * NQ + k;
        grad += g_grad_part[o];
        pg   += g_pg_part[o];
    }

    const float nrm    = g_norm[k];
    /* q@coefs = (p.g - p.l)/2 ; values = |q@coefs + p.l + free| = |(p.g + p.l)/2 + free| */
    const float values = fabsf(0.5f * (pg + pl) + free_coefs[k]);
    const float score  = (sqrtf(grad * 0.25f + values * nrm) - 0.5f * sqrtf(grad)) / nrm;
    out[(size_t)b * NQ + k] = score;
}

/* ============================================================ */
extern "C" void kernel_launch(void* const* d_in, const int* in_sizes, int n_in,
                              void* d_out, int out_size)
{
    const float* points = nullptr;
    const float* q      = nullptr;
    const float* l      = nullptr;
    const float* fr     = nullptr;

    for (int i = 0; i < n_in; i++) {
        switch (in_sizes[i]) {
            case NB * DIM:  points = (const float*)d_in[i]; break; /* 1048576 */
            case NM * NQ:   q      = (const float*)d_in[i]; break; /* 8404992 */
            case DIM * NQ:  l      = (const float*)d_in[i]; break; /* 32768   */
            case NQ:        fr     = (const float*)d_in[i]; break; /* 64      */
        }
    }
    /* positional fallback (metadata order: points, q_coefs, l_coefs, free_coefs) */
    if (!points) points = (const float*)d_in[0];
    if (!q)      q      = (const float*)d_in[1];
    if (!l)      l      = (const float*)d_in[2];
    if (!fr)     fr     = (const float*)d_in[3];

    const int smem = BTILE * PSTRIDE * 4; /* 132096 B */
    cudaFuncSetAttribute(hsq_main_kernel, cudaFuncAttributeMaxDynamicSharedMemorySize, smem);

    hsq_prep_kernel<<<PRE_BLOCKS, 256>>>(q);
    hsq_norm_kernel<<<1, 64>>>();

    dim3 grid(NB / BTILE, ESLICES); /* (32, 8) */
    hsq_main_kernel<<<grid, 256, smem>>>(points, l);

    hsq_score_kernel<<<NB / 4, 256>>>(points, l, fr, (float*)d_out);
}

// round 6
// speedup vs baseline: 5.5932x; 5.5932x over previous
#include <cuda_runtime.h>
#include <math.h>
#include <stdint.h>

#define DIM     512
#define NQ      64
#define NB      2048
#define NM      131328          /* 512*513/2 */
#define ESLICES 4
#define EC      128             /* e per CTA */
#define BTILE   64
#define PSTRIDE 516             /* padded P row stride (floats), 16B-aligned rows */
#define DCHUNK  64
#define NCHUNK  (EC * 8)        /* 1024 W chunks per CTA */
#define PRE_BLOCKS 1024

typedef unsigned long long ull;

/* ---- scratch (static device globals; no allocation APIs) ---- */
__device__ float g_W[(size_t)DIM * DIM * NQ];              /* [e][d][k]  64 MB */
__device__ float g_grad_part[(size_t)ESLICES * NB * NQ];
__device__ float g_pg_part  [(size_t)ESLICES * NB * NQ];
__device__ float g_nsq_part [(size_t)PRE_BLOCKS * NQ];
__device__ float g_norm[NQ];

/* ---- f32x2 packed-math helpers ---- */
__device__ __forceinline__ ull pk2(float lo, float hi) {
    ull r; asm("mov.b64 %0, {%1, %2};" : "=l"(r) : "f"(lo), "f"(hi)); return r;
}
__device__ __forceinline__ void fma2(ull& d, ull a, ull b) {   /* d = a*b + d */
    asm("fma.rn.f32x2 %0, %1, %2, %0;" : "+l"(d) : "l"(a), "l"(b));
}
__device__ __forceinline__ ull add2(ull a, ull b) {
    ull r; asm("add.rn.f32x2 %0, %1, %2;" : "=l"(r) : "l"(a), "l"(b)); return r;
}
__device__ __forceinline__ float2 up2(ull v) {
    float2 r; asm("mov.b64 {%0, %1}, %2;" : "=f"(r.x), "=f"(r.y) : "l"(v)); return r;
}

/* ============================================================
 * Kernel 1: build scaled symmetric W[e][d][k] + partial norms
 * ============================================================ */
__global__ __launch_bounds__(256) void hsq_prep_kernel(const float* __restrict__ q_coefs)
{
    const int t  = threadIdx.x;
    const int k  = t & 63;
    const int ms = t >> 6;
    float nsq = 0.0f;

    for (int base = blockIdx.x * 4; base < NM; base += gridDim.x * 4) {
        const int m = base + ms;
        if (m < NM) {
            const float q = q_coefs[(size_t)m * NQ + k];
            int i = (int)((2.0f * DIM + 1.0f -
                           sqrtf((float)(2 * DIM + 1) * (2 * DIM + 1) - 8.0f * (float)m)) * 0.5f);
            if (i < 0) i = 0;
            if (i > DIM - 1) i = DIM - 1;
            while (i > 0 && (i * DIM - (i * (i - 1)) / 2) > m) i--;
            while (i < DIM - 1 && ((i + 1) * DIM - ((i + 1) * i) / 2) <= m) i++;
            const int j = i + (m - (i * DIM - (i * (i - 1)) / 2));

            const float v = q * ((i == j) ? 2.0f : 1.4142135623730951f);
            g_W[((size_t)i * DIM + j) * NQ + k] = v;
            if (i != j)
                g_W[((size_t)j * DIM + i) * NQ + k] = v;
            nsq += q * q;
        }
    }

    __shared__ float red[256];
    red[t] = nsq;
    __syncthreads();
    if (ms == 0)
        g_nsq_part[(size_t)blockIdx.x * NQ + k] =
            red[k] + red[64 + k] + red[128 + k] + red[192 + k];
}

/* ============================================================
 * Kernel 2: finalize norms (fixed order)
 * ============================================================ */
__global__ void hsq_norm_kernel()
{
    const int k = threadIdx.x;
    float s = 0.0f;
    for (int b = 0; b < PRE_BLOCKS; b++)
        s += g_nsq_part[(size_t)b * NQ + k];
    g_norm[k] = sqrtf(s);
}

/* ============================================================
 * Kernel 3: main contraction — cp.async double-buffered W,
 * f32x2 register-tiled 4b x (2x f32x2 k) rank-512 update.
 * Grid (32 b-tiles, 4 e-slices) = 128 CTAs, 256 thr, occ 1.
 * ============================================================ */
__global__ __launch_bounds__(256, 1) void hsq_main_kernel(const float* __restrict__ points,
                                                          const float* __restrict__ l_coefs)
{
    extern __shared__ float smem[];
    float* ps  = smem;                          /* [BTILE][PSTRIDE]           */
    float* wsm = smem + BTILE * PSTRIDE;        /* 2 x [DCHUNK][NQ] = 8K fl   */

    const int bt = blockIdx.x;
    const int es = blockIdx.y;
    const int b0 = bt * BTILE;
    const int e0 = es * EC;
    const int t   = threadIdx.x;
    const int kc4 = (t & 15) * 4;
    const int br  = t >> 4;

    const uint32_t wsa = (uint32_t)__cvta_generic_to_shared(wsm);

    /* prefetch W chunk 0 (16 KB contiguous: [64d][64k] of e0) */
    {
        const float* src = g_W + (size_t)e0 * DIM * NQ;
        #pragma unroll
        for (int i = 0; i < 4; i++)
            asm volatile("cp.async.cg.shared.global [%0], [%1], 16;"
                         :: "r"(wsa + (uint32_t)((t + i * 256) * 16)),
                            "l"(src + (t + i * 256) * 4));
        asm volatile("cp.async.commit_group;");
    }

    /* stage P tile (coalesced) */
    for (int idx = t; idx < BTILE * DIM; idx += 256) {
        const int r = idx >> 9;
        const int c = idx & 511;
        ps[r * PSTRIDE + c] = points[(size_t)(b0 + r) * DIM + c];
    }

    ull grad2[4][2] = {};
    ull pg2[4][2]   = {};
    const float* pb = ps + (br * 4) * PSTRIDE;

    int ci = 0;
    for (int ee = 0; ee < EC; ee++) {
        ull acc[4][2] = {};

        for (int dc = 0; dc < 8; dc++, ci++) {
            /* issue next chunk into the other buffer */
            if (ci + 1 < NCHUNK) {
                const int nci = ci + 1;
                const float* src = g_W + ((size_t)(e0 + (nci >> 3)) * DIM + (nci & 7) * DCHUNK) * NQ;
                const uint32_t dst = wsa + (uint32_t)((nci & 1) * 16384);
                #pragma unroll
                for (int i = 0; i < 4; i++)
                    asm volatile("cp.async.cg.shared.global [%0], [%1], 16;"
                                 :: "r"(dst + (uint32_t)((t + i * 256) * 16)),
                                    "l"(src + (t + i * 256) * 4));
            }
            asm volatile("cp.async.commit_group;");
            asm volatile("cp.async.wait_group 1;");
            __syncthreads();

            const float* wt = wsm + (ci & 1) * (DCHUNK * NQ) + kc4;
            const float* pp = pb + dc * DCHUNK;

            #pragma unroll 4
            for (int d = 0; d < DCHUNK; d += 4) {
                /* W rows as natural f32x2 pairs (k0k1, k2k3) — zero pack cost */
                const double2 w0 = *(const double2*)(wt + (d + 0) * NQ);
                const double2 w1 = *(const double2*)(wt + (d + 1) * NQ);
                const double2 w2 = *(const double2*)(wt + (d + 2) * NQ);
                const double2 w3 = *(const double2*)(wt + (d + 3) * NQ);

                #pragma unroll
                for (int i = 0; i < 4; i++) {
                    const float4 pv = *(const float4*)(pp + i * PSTRIDE + d);
                    const ull px = pk2(pv.x, pv.x);
                    fma2(acc[i][0], px, __double_as_longlong(w0.x));
                    fma2(acc[i][1], px, __double_as_longlong(w0.y));
                    const ull py = pk2(pv.y, pv.y);
                    fma2(acc[i][0], py, __double_as_longlong(w1.x));
                    fma2(acc[i][1], py, __double_as_longlong(w1.y));
                    const ull pz = pk2(pv.z, pv.z);
                    fma2(acc[i][0], pz, __double_as_longlong(w2.x));
                    fma2(acc[i][1], pz, __double_as_longlong(w2.y));
                    const ull pw = pk2(pv.w, pv.w);
                    fma2(acc[i][0], pw, __double_as_longlong(w3.x));
                    fma2(acc[i][1], pw, __double_as_longlong(w3.y));
                }
            }
            __syncthreads();   /* all readers done before buffer reuse */
        }

        /* e-fold: g = acc + l ; grad += g*g ; pg += p_e * g */
        const int e = e0 + ee;
        const double2 lv = *(const double2*)(l_coefs + (size_t)e * NQ + kc4);
        #pragma unroll
        for (int i = 0; i < 4; i++) {
            const ull g0 = add2(acc[i][0], __double_as_longlong(lv.x));
            const ull g1 = add2(acc[i][1], __double_as_longlong(lv.y));
            const float pe = pb[i * PSTRIDE + e];
            const ull pe2 = pk2(pe, pe);
            fma2(grad2[i][0], g0, g0);
            fma2(grad2[i][1], g1, g1);
            fma2(pg2[i][0], pe2, g0);
            fma2(pg2[i][1], pe2, g1);
        }
    }

    #pragma unroll
    for (int i = 0; i < 4; i++) {
        const size_t o = ((size_t)es * NB + (b0 + br * 4 + i)) * NQ + kc4;
        const float2 ga = up2(grad2[i][0]);
        const float2 gb = up2(grad2[i][1]);
        *(float4*)(g_grad_part + o) = make_float4(ga.x, ga.y, gb.x, gb.y);
        const float2 pa = up2(pg2[i][0]);
        const float2 pc = up2(pg2[i][1]);
        *(float4*)(g_pg_part + o) = make_float4(pa.x, pa.y, pc.x, pc.y);
    }
}

/* ============================================================
 * Kernel 4: epilogue — sum partials, p.l dot, score formula
 * ============================================================ */
__global__ __launch_bounds__(256) void hsq_score_kernel(const float* __restrict__ points,
                                                        const float* __restrict__ l_coefs,
                                                        const float* __restrict__ free_coefs,
                                                        float* __restrict__ out)
{
    __shared__ float psh[4 * DIM];
    const int b0 = blockIdx.x * 4;
    const int t  = threadIdx.x;

    for (int idx = t; idx < 4 * DIM; idx += 256)
        psh[idx] = points[(size_t)b0 * DIM + idx];
    __syncthreads();

    const int k  = t & 63;
    const int bi = t >> 6;
    const int b  = b0 + bi;
    const float* pr = psh + bi * DIM;

    float pl = 0.0f;
    #pragma unroll 8
    for (int d = 0; d < DIM; d++)
        pl = fmaf(pr[d], l_coefs[(size_t)d * NQ + k], pl);

    float grad = 0.0f, pg = 0.0f;
    #pragma unroll
    for (int s = 0; s < ESLICES; s++) {
        const size_t o = ((size_t)s * NB + b) * NQ + k;
        grad += g_grad_part[o];
        pg   += g_pg_part[o];
    }

    const float nrm    = g_norm[k];
    /* values = |q@coefs + p.l + free| = |(p.g + p.l)/2 + free| */
    const float values = fabsf(0.5f * (pg + pl) + free_coefs[k]);
    const float score  = (sqrtf(grad * 0.25f + values * nrm) - 0.5f * sqrtf(grad)) / nrm;
    out[(size_t)b * NQ + k] = score;
}

/* ============================================================ */
extern "C" void kernel_launch(void* const* d_in, const int* in_sizes, int n_in,
                              void* d_out, int out_size)
{
    const float* points = nullptr;
    const float* q      = nullptr;
    const float* l      = nullptr;
    const float* fr     = nullptr;

    for (int i = 0; i < n_in; i++) {
        switch (in_sizes[i]) {
            case NB * DIM:  points = (const float*)d_in[i]; break;
            case NM * NQ:   q      = (const float*)d_in[i]; break;
            case DIM * NQ:  l      = (const float*)d_in[i]; break;
            case NQ:        fr     = (const float*)d_in[i]; break;
        }
    }
    if (!points) points = (const float*)d_in[0];
    if (!q)      q      = (const float*)d_in[1];
    if (!l)      l      = (const float*)d_in[2];
    if (!fr)     fr     = (const float*)d_in[3];

    const int smem = (BTILE * PSTRIDE + 2 * DCHUNK * NQ) * 4; /* 164864 B */
    cudaFuncSetAttribute(hsq_main_kernel, cudaFuncAttributeMaxDynamicSharedMemorySize, smem);

    hsq_prep_kernel<<<PRE_BLOCKS, 256>>>(q);
    hsq_norm_kernel<<<1, 64>>>();

    dim3 grid(NB / BTILE, ESLICES); /* (32, 4) — single wave on 148 SMs */
    hsq_main_kernel<<<grid, 256, smem>>>(points, l);

    hsq_score_kernel<<<NB / 4, 256>>>(points, l, fr, (float*)d_out);
}